// round 3
// baseline (speedup 1.0000x reference)
#include <cuda_runtime.h>
#include <math.h>

#define KP 8192
#define TT 4096
#define NTHREADS 512
#define EPT 16   // 512*16 = 8192

// 128MB scratch: transposed z, zc[t][k] = z[k][t]
__device__ float g_zc[(size_t)TT * KP];

// ---------------------------------------------------------------------------
// Tiled transpose: z [K, T] -> g_zc [T, K], coalesced both sides.
// ---------------------------------------------------------------------------
__global__ void transpose_kernel(const float* __restrict__ z) {
    __shared__ float tile[32][33];
    const int t0 = blockIdx.x * 32;
    const int k0 = blockIdx.y * 32;
    const int tx = threadIdx.x, ty = threadIdx.y;  // block (32, 8)
#pragma unroll
    for (int i = 0; i < 32; i += 8)
        tile[ty + i][tx] = z[(size_t)(k0 + ty + i) * TT + (t0 + tx)];
    __syncthreads();
#pragma unroll
    for (int i = 0; i < 32; i += 8)
        g_zc[(size_t)(t0 + ty + i) * KP + (k0 + tx)] = tile[tx][ty + i];
}

// ---------------------------------------------------------------------------
__device__ __forceinline__ void cp16(float* dst_smem, const float* src) {
    unsigned d = (unsigned)__cvta_generic_to_shared(dst_smem);
    asm volatile("cp.async.cg.shared.global [%0], [%1], 16;" :: "r"(d), "l"(src));
}

extern __shared__ float smem_f[];

// Shared layout:
//   sw   [8192] f32 : current particles
//   scdf [8192] f32 : unnormalized inclusive cumsum of exp(lw)
//   zbuf [2][8192]  : double-buffered z column (cp.async)
//   ubuf [2][8192]  : double-buffered u row    (cp.async)
//   sb   [8192] u16 : bucket -> start index
__global__ __launch_bounds__(NTHREADS, 1)
void smc_kernel(const float* __restrict__ x, const float* __restrict__ w0,
                const float* __restrict__ u, float* __restrict__ out) {
    float* sw   = smem_f;
    float* scdf = sw + KP;
    float* zbuf = scdf + KP;
    float* ubuf = zbuf + 2 * KP;
    unsigned short* sb = (unsigned short*)(ubuf + 2 * KP);
    __shared__ float sred[16];

    const int tid = threadIdx.x;
    const int lane = tid & 31;
    const int wid = tid >> 5;
    const int kbase = tid * EPT;

    // Prologue: prefetch steps 0 and 1 into the two buffers.
#pragma unroll
    for (int s = 0; s < 2; s++) {
        const float* zs = g_zc + (size_t)s * KP + kbase;
        const float* us = u + (size_t)s * KP + kbase;
        float* zd = zbuf + s * KP + kbase;
        float* ud = ubuf + s * KP + kbase;
#pragma unroll
        for (int q = 0; q < 4; q++) { cp16(zd + 4 * q, zs + 4 * q); cp16(ud + 4 * q, us + 4 * q); }
        asm volatile("cp.async.commit_group;");
    }

    // Initial particles: registers + shared copy (shared needed for gather).
    float wr[EPT];
    {
        const float4* w4 = (const float4*)(w0 + kbase);
#pragma unroll
        for (int q = 0; q < 4; q++) {
            float4 v = w4[q];
            wr[4*q+0] = v.x; wr[4*q+1] = v.y; wr[4*q+2] = v.z; wr[4*q+3] = v.w;
        }
    }
#pragma unroll
    for (int j = 0; j < EPT; j++) sw[kbase + j] = wr[j];
    // (cross-thread visibility guaranteed by the barriers inside step 0)

    float xt = __ldg(x);
    double acc = 0.0;

    for (int t = 0; t < TT; t++) {
        const int cur = t & 1;
        // Prefetch next x early (register pipeline).
        float xn = (t + 1 < TT) ? __ldg(x + t + 1) : 0.0f;

        // Wait for this step's z/u prefetch (own region only -> no barrier).
        asm volatile("cp.async.wait_group 1;");

        // lw[k] = x*z - 0.5*(z-w)^2 ; weights exp(lw) with M = 0 (safe range:
        // resampling only permutes w among the original N(0,1) draws).
        // S = local inclusive prefix of weights.
        float S[EPT];
        float run = 0.0f;
        {
            const float4* zz = (const float4*)(zbuf + cur * KP + kbase);
#pragma unroll
            for (int q = 0; q < 4; q++) {
                float4 v = zz[q];
                float zv[4] = {v.x, v.y, v.z, v.w};
#pragma unroll
                for (int r = 0; r < 4; r++) {
                    float d = zv[r] - wr[4*q+r];
                    float lwv = fmaf(xt, zv[r], -0.5f * d * d);
                    run += __expf(fminf(lwv, 80.0f));   // clamp: overflow guard
                    S[4*q+r] = run;
                }
            }
        }
        const float ts = run;

        // Intra-warp Kogge-Stone scan of per-thread totals.
        float sc = ts;
#pragma unroll
        for (int o = 1; o < 32; o <<= 1) {
            float q = __shfl_up_sync(0xffffffffu, sc, o);
            if (lane >= o) sc += q;
        }
        if (lane == 31) sred[wid] = sc;
        __syncthreads();                                   // bar A

        // Every thread sums the 16 warp totals sequentially -> bitwise-uniform
        // 'tot' (and 'scale'); 'base' = prefix before my warp.
        float base = 0.0f, tot = 0.0f;
#pragma unroll
        for (int w = 0; w < 16; w++) {
            float v = sred[w];
            if (w == wid) base = tot;
            tot += v;
        }
        const float off = base + (sc - ts);

        // Store absolute cdf; keep absolute values in S for the bucket build.
        {
            float4* c4 = (float4*)(scdf + kbase);
#pragma unroll
            for (int q = 0; q < 4; q++) {
                float4 v;
                v.x = off + S[4*q+0]; v.y = off + S[4*q+1];
                v.z = off + S[4*q+2]; v.w = off + S[4*q+3];
                S[4*q+0] = v.x; S[4*q+1] = v.y; S[4*q+2] = v.z; S[4*q+3] = v.w;
                c4[q] = v;
            }
        }
        __syncthreads();                                   // bar B1 (cdf visible)

        // Bucket table: sb[b] = first element covering bucket b. Range start is
        // read from the STORED neighbor cdf value -> bitwise-consistent floors,
        // gapless coverage. Heavy ranges (>32 buckets) filled warp-cooperatively.
        const float scale = (float)KP / tot;
        int bprev = (tid == 0) ? -1 : (int)(scdf[kbase - 1] * scale);
#pragma unroll
        for (int j = 0; j < EPT; j++) {
            int b1 = (int)(S[j] * scale);
            if (b1 > KP - 1) b1 = KP - 1;
            const int val = kbase + j;
            const int cov = b1 - bprev;
            unsigned hv = __ballot_sync(0xffffffffu, cov > 32);
            if (cov <= 32) {
                for (int b = bprev + 1; b <= b1; b++) sb[b] = (unsigned short)val;
            }
            while (hv) {
                int src = __ffs(hv) - 1; hv &= hv - 1;
                int hb0 = __shfl_sync(0xffffffffu, bprev, src);
                int hb1 = __shfl_sync(0xffffffffu, b1, src);
                int hvv = __shfl_sync(0xffffffffu, val, src);
                for (int b = hb0 + 1 + lane; b <= hb1; b += 32)
                    sb[b] = (unsigned short)hvv;
            }
            if (b1 > bprev) bprev = b1;
        }
        __syncthreads();                                   // bar B (table ready)

        // Search: bucket start + lockstep advance (16-way ILP per LDS round).
        int ii[EPT]; float tg[EPT];
        {
            const float4* uu4 = (const float4*)(ubuf + cur * KP + kbase);
#pragma unroll
            for (int q = 0; q < 4; q++) {
                float4 v = uu4[q];
                float uv[4] = {v.x, v.y, v.z, v.w};
#pragma unroll
                for (int r = 0; r < 4; r++) {
                    const int j = 4*q + r;
                    tg[j] = uv[r] * tot;
                    int b = (int)(uv[r] * (float)KP);
                    if (b > KP - 1) b = KP - 1;
                    ii[j] = sb[b];
                }
            }
        }
        bool more = true;
        while (more) {
            more = false;
#pragma unroll
            for (int j = 0; j < EPT; j++) {
                if (ii[j] < KP - 1 && scdf[ii[j]] < tg[j]) { ii[j]++; more = true; }
            }
        }
#pragma unroll
        for (int j = 0; j < EPT; j++) wr[j] = sw[ii[j]];   // gather old particles
        __syncthreads();                                   // bar C (gathers done)
        {
            float4* s4 = (float4*)(sw + kbase);
#pragma unroll
            for (int q = 0; q < 4; q++) {
                float4 v;
                v.x = wr[4*q+0]; v.y = wr[4*q+1]; v.z = wr[4*q+2]; v.w = wr[4*q+3];
                s4[q] = v;
            }
        }

        if (tid == 0) {
            // lme = log(tot) - log(K) - 0.5*log(2*pi) - 0.5*x^2
            acc += (double)(logf(tot) - 9.010913347279289f - 0.9189385332046727f)
                 - 0.5 * (double)xt * (double)xt;
        }
        xt = xn;

        // Prefetch step t+2 into the buffer just consumed.
        if (t + 2 < TT) {
            const float* zs = g_zc + (size_t)(t + 2) * KP + kbase;
            const float* us = u + (size_t)(t + 2) * KP + kbase;
            float* zd = zbuf + cur * KP + kbase;
            float* ud = ubuf + cur * KP + kbase;
#pragma unroll
            for (int q = 0; q < 4; q++) { cp16(zd + 4*q, zs + 4*q); cp16(ud + 4*q, us + 4*q); }
        }
        asm volatile("cp.async.commit_group;");  // unconditional: keep group count aligned
    }

    if (tid == 0) out[0] = (float)acc;
}

// ---------------------------------------------------------------------------
extern "C" void kernel_launch(void* const* d_in, const int* in_sizes, int n_in,
                              void* d_out, int out_size) {
    const float* x  = (const float*)d_in[0];   // [T]
    const float* w0 = (const float*)d_in[1];   // [K]
    const float* z  = (const float*)d_in[2];   // [K, T]
    const float* u  = (const float*)d_in[3];   // [T, K]
    float* out = (float*)d_out;

    dim3 tb(32, 8);
    dim3 tg(TT / 32, KP / 32);
    transpose_kernel<<<tg, tb>>>(z);

    const size_t smem = (size_t)6 * KP * sizeof(float)      // sw, scdf, zbuf*2, ubuf*2
                      + (size_t)KP * sizeof(unsigned short); // sb
    cudaFuncSetAttribute(smc_kernel,
                         cudaFuncAttributeMaxDynamicSharedMemorySize, (int)smem);
    smc_kernel<<<1, NTHREADS, smem>>>(x, w0, u, out);
}

// round 4
// speedup vs baseline: 1.1431x; 1.1431x over previous
#include <cuda_runtime.h>
#include <math.h>

#define KP 8192
#define TT 4096
#define NTHREADS 512
#define EPT 16   // 512*16 = 8192

// 128MB scratch: transposed z, zc[t][k] = z[k][t]
__device__ float g_zc[(size_t)TT * KP];

// ---------------------------------------------------------------------------
// Tiled transpose: z [K, T] -> g_zc [T, K], coalesced both sides.
// ---------------------------------------------------------------------------
__global__ void transpose_kernel(const float* __restrict__ z) {
    __shared__ float tile[32][33];
    const int t0 = blockIdx.x * 32;
    const int k0 = blockIdx.y * 32;
    const int tx = threadIdx.x, ty = threadIdx.y;  // block (32, 8)
#pragma unroll
    for (int i = 0; i < 32; i += 8)
        tile[ty + i][tx] = z[(size_t)(k0 + ty + i) * TT + (t0 + tx)];
    __syncthreads();
#pragma unroll
    for (int i = 0; i < 32; i += 8)
        g_zc[(size_t)(t0 + ty + i) * KP + (k0 + tx)] = tile[tx][ty + i];
}

// ---------------------------------------------------------------------------
__device__ __forceinline__ void cp16(float* dst_smem, const float* src) {
    unsigned d = (unsigned)__cvta_generic_to_shared(dst_smem);
    asm volatile("cp.async.cg.shared.global [%0], [%1], 16;" :: "r"(d), "l"(src));
}

extern __shared__ float smem_f[];

// Shared layout:
//   sw   [8192] f32   : current particles
//   scdf [8192] f32   : unnormalized inclusive cumsum of exp(lw)
//   zbuf [2][8192]    : double-buffered z column (cp.async)
//   ubuf [2][8192]    : double-buffered u row    (cp.async)
//   sb   [8193] u16   : bucket -> first covering element; sb[KP] = KP-1 sentinel
__global__ __launch_bounds__(NTHREADS, 1)
void smc_kernel(const float* __restrict__ x, const float* __restrict__ w0,
                const float* __restrict__ u, float* __restrict__ out) {
    float* sw   = smem_f;
    float* scdf = sw + KP;
    float* zbuf = scdf + KP;
    float* ubuf = zbuf + 2 * KP;
    unsigned short* sb = (unsigned short*)(ubuf + 2 * KP);
    __shared__ float sred[16];

    const int tid = threadIdx.x;
    const int lane = tid & 31;
    const int wid = tid >> 5;
    const int kbase = tid * EPT;

    // Prologue: prefetch steps 0 and 1 into the two buffers.
#pragma unroll
    for (int s = 0; s < 2; s++) {
        const float* zs = g_zc + (size_t)s * KP + kbase;
        const float* us = u + (size_t)s * KP + kbase;
        float* zd = zbuf + s * KP + kbase;
        float* ud = ubuf + s * KP + kbase;
#pragma unroll
        for (int q = 0; q < 4; q++) { cp16(zd + 4 * q, zs + 4 * q); cp16(ud + 4 * q, us + 4 * q); }
        asm volatile("cp.async.commit_group;");
    }

    if (tid == 0) sb[KP] = (unsigned short)(KP - 1);  // sentinel, set once

    // Initial particles: registers + shared copy (shared needed for gather).
    float wr[EPT];
    {
        const float4* w4 = (const float4*)(w0 + kbase);
#pragma unroll
        for (int q = 0; q < 4; q++) {
            float4 v = w4[q];
            wr[4*q+0] = v.x; wr[4*q+1] = v.y; wr[4*q+2] = v.z; wr[4*q+3] = v.w;
        }
    }
#pragma unroll
    for (int j = 0; j < EPT; j++) sw[kbase + j] = wr[j];
    // (cross-thread visibility guaranteed by the barriers inside step 0)

    float xt = __ldg(x);
    double acc = 0.0;

    for (int t = 0; t < TT; t++) {
        const int cur = t & 1;
        float xn = (t + 1 < TT) ? __ldg(x + t + 1) : 0.0f;

        // Wait for this step's z/u prefetch (own region only -> no barrier).
        asm volatile("cp.async.wait_group 1;");

        // lw[k] = x*z - 0.5*(z-w)^2 ; weights exp(lw) with M=0 (safe range:
        // resampling only permutes w among the original N(0,1) draws).
        float S[EPT];
        float run = 0.0f;
        {
            const float4* zz = (const float4*)(zbuf + cur * KP + kbase);
#pragma unroll
            for (int q = 0; q < 4; q++) {
                float4 v = zz[q];
                float zv[4] = {v.x, v.y, v.z, v.w};
#pragma unroll
                for (int r = 0; r < 4; r++) {
                    float d = zv[r] - wr[4*q+r];
                    float lwv = fmaf(xt, zv[r], -0.5f * d * d);
                    run += __expf(fminf(lwv, 80.0f));
                    S[4*q+r] = run;
                }
            }
        }
        const float ts = run;

        // Intra-warp Kogge-Stone scan of per-thread totals.
        float sc = ts;
#pragma unroll
        for (int o = 1; o < 32; o <<= 1) {
            float q = __shfl_up_sync(0xffffffffu, sc, o);
            if (lane >= o) sc += q;
        }
        if (lane == 31) sred[wid] = sc;
        __syncthreads();                                   // bar A

        // Every thread re-sums the 16 warp totals -> bitwise-uniform tot/scale.
        float base = 0.0f, tot = 0.0f;
#pragma unroll
        for (int w = 0; w < 16; w++) {
            float v = sred[w];
            if (w == wid) base = tot;
            tot += v;
        }
        const float off = base + (sc - ts);

        // Store absolute cdf; keep absolute values in S for the bucket build.
        {
            float4* c4 = (float4*)(scdf + kbase);
#pragma unroll
            for (int q = 0; q < 4; q++) {
                float4 v;
                v.x = off + S[4*q+0]; v.y = off + S[4*q+1];
                v.z = off + S[4*q+2]; v.w = off + S[4*q+3];
                S[4*q+0] = v.x; S[4*q+1] = v.y; S[4*q+2] = v.z; S[4*q+3] = v.w;
                c4[q] = v;
            }
        }
        __syncthreads();                                   // bar B1 (cdf visible)

        // Bucket table: sb[b] = first element covering bucket b. Range start
        // from the STORED neighbor cdf -> bitwise-consistent floors, gapless.
        // Heavy ranges (>32 buckets) filled warp-cooperatively.
        const float scale = (float)KP / tot;
        int bprev = (tid == 0) ? -1 : (int)(scdf[kbase - 1] * scale);
#pragma unroll
        for (int j = 0; j < EPT; j++) {
            int b1 = (int)(S[j] * scale);
            if (b1 > KP - 1) b1 = KP - 1;
            const int val = kbase + j;
            const int cov = b1 - bprev;
            unsigned hv = __ballot_sync(0xffffffffu, cov > 32);
            if (cov <= 32) {
                for (int b = bprev + 1; b <= b1; b++) sb[b] = (unsigned short)val;
            }
            while (hv) {
                int src = __ffs(hv) - 1; hv &= hv - 1;
                int hb0 = __shfl_sync(0xffffffffu, bprev, src);
                int hb1 = __shfl_sync(0xffffffffu, b1, src);
                int hvv = __shfl_sync(0xffffffffu, val, src);
                for (int b = hb0 + 1 + lane; b <= hb1; b += 32)
                    sb[b] = (unsigned short)hvv;
            }
            if (b1 > bprev) bprev = b1;
        }
        __syncthreads();                                   // bar B (table ready)

        // Search: bucket bracket [sb[b], sb[b+1]] + lockstep binary search.
        // Two groups of 8 to bound register pressure; 8-way LDS ILP per round.
#pragma unroll
        for (int g = 0; g < 2; g++) {
            int lo[8], hi[8]; float tg[8];
            {
                const float4* uu4 = (const float4*)(ubuf + cur * KP + kbase + g * 8);
#pragma unroll
                for (int q = 0; q < 2; q++) {
                    float4 v = uu4[q];
                    float uvv[4] = {v.x, v.y, v.z, v.w};
#pragma unroll
                    for (int r = 0; r < 4; r++) {
                        const int j = 4*q + r;
                        tg[j] = uvv[r] * tot;
                        int b = (int)(uvv[r] * (float)KP);
                        if (b > KP - 1) b = KP - 1;
                        lo[j] = sb[b];
                        hi[j] = sb[b + 1];   // certified upper bracket
                    }
                }
            }
            bool more = true;
            while (more) {
                more = false;
#pragma unroll
                for (int j = 0; j < 8; j++) {
                    if (lo[j] < hi[j]) {
                        int mid = (lo[j] + hi[j]) >> 1;
                        if (scdf[mid] < tg[j]) lo[j] = mid + 1; else hi[j] = mid;
                        more = true;
                    }
                }
            }
#pragma unroll
            for (int j = 0; j < 8; j++) wr[g * 8 + j] = sw[lo[j]];  // gather
        }
        __syncthreads();                                   // bar C (gathers done)
        {
            float4* s4 = (float4*)(sw + kbase);
#pragma unroll
            for (int q = 0; q < 4; q++) {
                float4 v;
                v.x = wr[4*q+0]; v.y = wr[4*q+1]; v.z = wr[4*q+2]; v.w = wr[4*q+3];
                s4[q] = v;
            }
        }

        if (tid == 0) {
            // lme = log(tot) - log(K) - 0.5*log(2*pi) - 0.5*x^2
            acc += (double)(logf(tot) - 9.010913347279289f - 0.9189385332046727f)
                 - 0.5 * (double)xt * (double)xt;
        }
        xt = xn;

        // Prefetch step t+2 into the buffer just consumed.
        if (t + 2 < TT) {
            const float* zs = g_zc + (size_t)(t + 2) * KP + kbase;
            const float* us = u + (size_t)(t + 2) * KP + kbase;
            float* zd = zbuf + cur * KP + kbase;
            float* ud = ubuf + cur * KP + kbase;
#pragma unroll
            for (int q = 0; q < 4; q++) { cp16(zd + 4*q, zs + 4*q); cp16(ud + 4*q, us + 4*q); }
        }
        asm volatile("cp.async.commit_group;");  // unconditional: keep group count aligned
    }

    if (tid == 0) out[0] = (float)acc;
}

// ---------------------------------------------------------------------------
extern "C" void kernel_launch(void* const* d_in, const int* in_sizes, int n_in,
                              void* d_out, int out_size) {
    const float* x  = (const float*)d_in[0];   // [T]
    const float* w0 = (const float*)d_in[1];   // [K]
    const float* z  = (const float*)d_in[2];   // [K, T]
    const float* u  = (const float*)d_in[3];   // [T, K]
    float* out = (float*)d_out;

    dim3 tb(32, 8);
    dim3 tg(TT / 32, KP / 32);
    transpose_kernel<<<tg, tb>>>(z);

    const size_t smem = (size_t)6 * KP * sizeof(float)        // sw, scdf, zbuf*2, ubuf*2
                      + (size_t)(KP + 8) * sizeof(unsigned short); // sb + sentinel pad
    cudaFuncSetAttribute(smc_kernel,
                         cudaFuncAttributeMaxDynamicSharedMemorySize, (int)smem);
    smc_kernel<<<1, NTHREADS, smem>>>(x, w0, u, out);
}